// round 1
// baseline (speedup 1.0000x reference)
#include <cuda_runtime.h>
#include <math.h>

#define N_NODES 50000
#define N_EDGES 500000
#define NF      128
#define NH      4
#define NEG_SLOPE 0.2f
#define BN_EPS 1e-5f

// ---------------- scratch (device globals; no allocation allowed) ----------
__device__ float g_h [N_NODES * NF];
__device__ float g_h1[N_NODES * NF];
__device__ float g_fs[N_NODES * NF];
__device__ float g_h2[N_NODES * NF];
__device__ float g_el[N_NODES * NH];
__device__ float g_er[N_NODES * NH];
__device__ float g_mx[N_NODES * NH];
__device__ float g_sm[N_NODES * NH];
__device__ float g_ex[N_EDGES * NH];
__device__ double g_sum[NF];
__device__ double g_sq [NF];

// ---------------- utility kernels ----------------
__global__ void fill_f(float* p, float v, int n) {
    int i = blockIdx.x * blockDim.x + threadIdx.x;
    if (i < n) p[i] = v;
}

__global__ void zero_stats() {
    g_sum[threadIdx.x] = 0.0;
    g_sq[threadIdx.x]  = 0.0;
}

// ---------------- 50000x128 @ 128x128 SGEMM (+ optional attn epilogue) -----
// BM=64, BN=128, BK=16, 512 threads, thread tile 4x4.
__global__ __launch_bounds__(512)
void gemm128(const float* __restrict__ A, const float* __restrict__ W,
             const float* __restrict__ bias, float* __restrict__ C,
             const float* __restrict__ al, const float* __restrict__ ar,
             float* __restrict__ elo, float* __restrict__ ero) {
    __shared__ float As[16][64];
    __shared__ float Ws[16][128];

    const int tid = threadIdx.x;
    const int ty = tid >> 5;     // 0..15 (= warp id) -> rows ty*4..ty*4+3
    const int tx = tid & 31;     // lane -> cols tx*4..tx*4+3
    const int rb = blockIdx.x * 64;

    float acc[4][4];
#pragma unroll
    for (int i = 0; i < 4; i++)
#pragma unroll
        for (int j = 0; j < 4; j++) acc[i][j] = 0.f;

    for (int kc = 0; kc < 128; kc += 16) {
        if (tid < 256) {
            int row = tid >> 2;
            int kq  = (tid & 3) * 4;
            float4 v = make_float4(0.f, 0.f, 0.f, 0.f);
            if (rb + row < N_NODES)
                v = *(const float4*)&A[(size_t)(rb + row) * NF + kc + kq];
            As[kq + 0][row] = v.x;
            As[kq + 1][row] = v.y;
            As[kq + 2][row] = v.z;
            As[kq + 3][row] = v.w;
        }
        {
            int kr = tid >> 5;
            int c4 = (tid & 31) * 4;
            float4 v = *(const float4*)&W[(kc + kr) * NF + c4];
            *(float4*)&Ws[kr][c4] = v;
        }
        __syncthreads();
#pragma unroll
        for (int kk = 0; kk < 16; kk++) {
            float4 av = *(float4*)&As[kk][ty * 4];
            float4 bv = *(float4*)&Ws[kk][tx * 4];
            float a[4] = {av.x, av.y, av.z, av.w};
            float b[4] = {bv.x, bv.y, bv.z, bv.w};
#pragma unroll
            for (int i = 0; i < 4; i++)
#pragma unroll
                for (int j = 0; j < 4; j++) acc[i][j] = fmaf(a[i], b[j], acc[i][j]);
        }
        __syncthreads();
    }

    const int cb = tx * 4;
    float4 b4 = make_float4(0.f, 0.f, 0.f, 0.f);
    if (bias) b4 = *(const float4*)&bias[cb];
    float alv[4] = {0, 0, 0, 0}, arv[4] = {0, 0, 0, 0};
    if (elo) {
#pragma unroll
        for (int j = 0; j < 4; j++) { alv[j] = al[cb + j]; arv[j] = ar[cb + j]; }
    }

#pragma unroll
    for (int i = 0; i < 4; i++) {
        int row = rb + ty * 4 + i;
        float o0 = acc[i][0] + b4.x;
        float o1 = acc[i][1] + b4.y;
        float o2 = acc[i][2] + b4.z;
        float o3 = acc[i][3] + b4.w;
        if (row < N_NODES)
            *(float4*)&C[(size_t)row * NF + cb] = make_float4(o0, o1, o2, o3);
        if (elo) {
            float p = acc[i][0] * alv[0] + acc[i][1] * alv[1] +
                      acc[i][2] * alv[2] + acc[i][3] * alv[3];
            float q = acc[i][0] * arv[0] + acc[i][1] * arv[1] +
                      acc[i][2] * arv[2] + acc[i][3] * arv[3];
#pragma unroll
            for (int off = 4; off >= 1; off >>= 1) {
                p += __shfl_down_sync(0xffffffffu, p, off, 8);
                q += __shfl_down_sync(0xffffffffu, q, off, 8);
            }
            if ((tx & 7) == 0 && row < N_NODES) {
                int hh = tx >> 3;
                elo[row * NH + hh] = p;
                ero[row * NH + hh] = q;
            }
        }
    }
}

// ---------------- edge softmax passes ----------------
__device__ __forceinline__ void atomicMaxF(float* addr, float val) {
    if (val >= 0.f) atomicMax((int*)addr, __float_as_int(val));
    else            atomicMin((unsigned int*)addr, __float_as_uint(val));
}

__global__ void edge_max(const int* __restrict__ src, const int* __restrict__ dst,
                         const float* __restrict__ el, const float* __restrict__ er,
                         float* __restrict__ mx) {
    int idx = blockIdx.x * blockDim.x + threadIdx.x;
    if (idx >= N_EDGES * NH) return;
    int e = idx >> 2, h = idx & 3;
    int s = src[e], d = dst[e];
    float v = el[s * NH + h] + er[d * NH + h];
    v = v > 0.f ? v : NEG_SLOPE * v;
    atomicMaxF(&mx[d * NH + h], v);
}

__global__ void edge_sum(const int* __restrict__ src, const int* __restrict__ dst,
                         const float* __restrict__ el, const float* __restrict__ er,
                         const float* __restrict__ mx, float* __restrict__ ex,
                         float* __restrict__ sm) {
    int idx = blockIdx.x * blockDim.x + threadIdx.x;
    if (idx >= N_EDGES * NH) return;
    int e = idx >> 2, h = idx & 3;
    int s = src[e], d = dst[e];
    float v = el[s * NH + h] + er[d * NH + h];
    v = v > 0.f ? v : NEG_SLOPE * v;
    float t = expf(v - mx[d * NH + h]);
    ex[idx] = t;
    atomicAdd(&sm[d * NH + h], t);
}

// one warp per edge: lane L handles fs columns L*4..L*4+3 (head = L>>3)
__global__ __launch_bounds__(256)
void edge_msg(const int* __restrict__ src, const int* __restrict__ dst,
              const float* __restrict__ fs, const float* __restrict__ ex,
              const float* __restrict__ sm, float* __restrict__ h2) {
    int gw = (blockIdx.x * blockDim.x + threadIdx.x) >> 5;
    int lane = threadIdx.x & 31;
    if (gw >= N_EDGES) return;
    int s = src[gw], d = dst[gw];
    int h = lane >> 3;
    float alpha = ex[gw * NH + h] / sm[d * NH + h];
    float4 f = *(const float4*)&fs[(size_t)s * NF + lane * 4];
    float* o = &h2[(size_t)d * NF + lane * 4];
    atomicAdd(o + 0, alpha * f.x);
    atomicAdd(o + 1, alpha * f.y);
    atomicAdd(o + 2, alpha * f.z);
    atomicAdd(o + 3, alpha * f.w);
}

// ---------------- layer finalize: t = h1 + relu(h2 + bias), + BN stats -----
#define RPB 128
__global__ void finalize_stats(const float* __restrict__ h1, const float* __restrict__ h2,
                               const float* __restrict__ cb0, const float* __restrict__ cb1,
                               float* __restrict__ t) {
    int col = threadIdx.x;
    float bias = cb0[col] + cb1[col];
    int r0 = blockIdx.x * RPB;
    double s = 0.0, s2 = 0.0;
    for (int r = 0; r < RPB; r++) {
        int row = r0 + r;
        if (row >= N_NODES) break;
        float v = h2[(size_t)row * NF + col] + bias;
        v = v > 0.f ? v : 0.f;
        v += h1[(size_t)row * NF + col];
        t[(size_t)row * NF + col] = v;
        s += v;
        s2 += (double)v * (double)v;
    }
    atomicAdd(&g_sum[col], s);
    atomicAdd(&g_sq[col], s2);
}

__global__ void stats128(const float* __restrict__ x) {
    int col = threadIdx.x;
    int r0 = blockIdx.x * RPB;
    double s = 0.0, s2 = 0.0;
    for (int r = 0; r < RPB; r++) {
        int row = r0 + r;
        if (row >= N_NODES) break;
        float v = x[(size_t)row * NF + col];
        s += v;
        s2 += (double)v * (double)v;
    }
    atomicAdd(&g_sum[col], s);
    atomicAdd(&g_sq[col], s2);
}

__global__ void normalize128(const float* __restrict__ x, const float* __restrict__ g,
                             const float* __restrict__ b, float* __restrict__ y,
                             int do_relu) {
    int col = threadIdx.x;
    double mu = g_sum[col] / (double)N_NODES;
    double var = g_sq[col] / (double)N_NODES - mu * mu;
    float sc = g[col] * rsqrtf((float)var + BN_EPS);
    float sh = b[col] - (float)mu * sc;
    int r0 = blockIdx.x * RPB;
    for (int r = 0; r < RPB; r++) {
        int row = r0 + r;
        if (row >= N_NODES) break;
        float v = x[(size_t)row * NF + col] * sc + sh;
        if (do_relu) v = v > 0.f ? v : 0.f;
        y[(size_t)row * NF + col] = v;
    }
}

// ---------------- final 128 -> 16 GEMM ----------------
__global__ __launch_bounds__(128)
void gemm_out(const float* __restrict__ x, const float* __restrict__ W2,
              const float* __restrict__ b2, float* __restrict__ out) {
    __shared__ float xs[8][NF];
    int tid = threadIdx.x;
    int r0 = blockIdx.x * 8;
#pragma unroll
    for (int i = 0; i < 8; i++) {
        int row = r0 + i;
        xs[i][tid] = (row < N_NODES) ? x[(size_t)row * NF + tid] : 0.f;
    }
    __syncthreads();
    int row = tid >> 4;
    int c = tid & 15;
    float acc = b2[c];
#pragma unroll 8
    for (int k = 0; k < NF; k++) acc = fmaf(xs[row][k], W2[k * 16 + c], acc);
    if (r0 + row < N_NODES) out[(size_t)(r0 + row) * 16 + c] = acc;
}

// ---------------- host ----------------
extern "C" void kernel_launch(void* const* d_in, const int* in_sizes, int n_in,
                              void* d_out, int out_size) {
    const float* feat     = (const float*)d_in[0];
    const float* fc_W     = (const float*)d_in[1];   // [2][2][128][128]
    const float* attn_l   = (const float*)d_in[2];   // [2][2][4][32] -> [..][128]
    const float* attn_r   = (const float*)d_in[3];
    const float* conv_b   = (const float*)d_in[4];   // [2][2][128]
    const float* skip_W   = (const float*)d_in[5];   // [2][128][128]
    const float* skip_b   = (const float*)d_in[6];   // [2][128]
    const float* norm_g   = (const float*)d_in[7];
    const float* norm_b   = (const float*)d_in[8];
    const float* clf_W1   = (const float*)d_in[9];
    const float* clf_b1   = (const float*)d_in[10];
    const float* clf_g    = (const float*)d_in[11];
    const float* clf_b    = (const float*)d_in[12];
    const float* clf_W2   = (const float*)d_in[13];
    const float* clf_b2   = (const float*)d_in[14];
    const int*   src      = (const int*)d_in[15];    // [2][500000]
    const int*   dst      = (const int*)d_in[16];
    float* out = (float*)d_out;

    float *h, *h1, *fs, *h2, *el, *er, *mx, *sm, *ex;
    cudaGetSymbolAddress((void**)&h,  g_h);
    cudaGetSymbolAddress((void**)&h1, g_h1);
    cudaGetSymbolAddress((void**)&fs, g_fs);
    cudaGetSymbolAddress((void**)&h2, g_h2);
    cudaGetSymbolAddress((void**)&el, g_el);
    cudaGetSymbolAddress((void**)&er, g_er);
    cudaGetSymbolAddress((void**)&mx, g_mx);
    cudaGetSymbolAddress((void**)&sm, g_sm);
    cudaGetSymbolAddress((void**)&ex, g_ex);

    const int gemm_grid = (N_NODES + 63) / 64;             // 782
    const int eh_grid   = (N_EDGES * NH + 255) / 256;      // 7813
    const int msg_grid  = (N_EDGES * 32 + 255) / 256;      // 62500
    const int fill_big  = (N_NODES * NF + 255) / 256;
    const int fill_sm   = (N_NODES * NH + 255) / 256;
    const int bn_grid   = (N_NODES + RPB - 1) / RPB;       // 391

    const float* hin = feat;
    for (int l = 0; l < 2; l++) {
        // skip linear: h1 = hin @ skip_W[l] + skip_b[l]
        gemm128<<<gemm_grid, 512>>>(hin, skip_W + l * NF * NF, skip_b + l * NF,
                                    h1, nullptr, nullptr, nullptr, nullptr);
        fill_f<<<fill_big, 256>>>(h2, 0.f, N_NODES * NF);

        for (int r = 0; r < 2; r++) {
            int lr = l * 2 + r;
            // fs = hin @ fc_W[l,r]; el/er fused in epilogue
            gemm128<<<gemm_grid, 512>>>(hin, fc_W + (size_t)lr * NF * NF, nullptr,
                                        fs, attn_l + lr * NF, attn_r + lr * NF, el, er);
            fill_f<<<fill_sm, 256>>>(mx, -INFINITY, N_NODES * NH);
            fill_f<<<fill_sm, 256>>>(sm, 0.f, N_NODES * NH);
            const int* sr = src + (size_t)r * N_EDGES;
            const int* dr = dst + (size_t)r * N_EDGES;
            edge_max<<<eh_grid, 256>>>(sr, dr, el, er, mx);
            edge_sum<<<eh_grid, 256>>>(sr, dr, el, er, mx, ex, sm);
            edge_msg<<<msg_grid, 256>>>(sr, dr, fs, ex, sm, h2);
        }

        zero_stats<<<1, 128>>>();
        // t = h1 + relu(h2 + sum_r conv_bias) (into fs scratch) + BN stats
        finalize_stats<<<bn_grid, 128>>>(h1, h2, conv_b + (l * 2 + 0) * NF,
                                         conv_b + (l * 2 + 1) * NF, fs);
        normalize128<<<bn_grid, 128>>>(fs, norm_g + l * NF, norm_b + l * NF, h, 0);
        hin = h;
    }

    // classifier
    gemm128<<<gemm_grid, 512>>>(h, clf_W1, clf_b1, h1, nullptr, nullptr, nullptr, nullptr);
    zero_stats<<<1, 128>>>();
    stats128<<<bn_grid, 128>>>(h1);
    normalize128<<<bn_grid, 128>>>(h1, clf_g, clf_b, fs, 1);
    gemm_out<<<(N_NODES + 7) / 8, 128>>>(fs, clf_W2, clf_b2, out);
}

// round 2
// speedup vs baseline: 1.3201x; 1.3201x over previous
#include <cuda_runtime.h>
#include <math.h>

#define N_NODES 50000
#define N_EDGES 500000
#define NF      128
#define NH      4
#define NEG_SLOPE 0.2f
#define BN_EPS 1e-5f

// ---------------- scratch (device globals; no allocation allowed) ----------
__device__ float g_h [N_NODES * NF];
__device__ float g_h1[N_NODES * NF];
__device__ float g_fs[N_NODES * NF];
__device__ float g_h2[N_NODES * NF];
__device__ float g_el[N_NODES * NH];
__device__ float g_er[N_NODES * NH];
__device__ float g_mx[N_NODES * NH];
__device__ float g_sm[N_NODES * NH];
__device__ float g_ex[N_EDGES * NH];
__device__ double g_sum[NF];
__device__ double g_sq [NF];

// ---------------- utility kernels ----------------
__global__ void fill_f4(float4* p, float v, int n4) {
    int i = blockIdx.x * blockDim.x + threadIdx.x;
    if (i < n4) p[i] = make_float4(v, v, v, v);
}

__global__ void zero_stats() {
    g_sum[threadIdx.x] = 0.0;
    g_sq[threadIdx.x]  = 0.0;
}

// ---------------- 50000x128 @ 128x128 SGEMM (+ optional attn epilogue) -----
// BM=128, BN=128, BK=8, 256 threads, 8x8 microtile -> 1B smem / FLOP.
__global__ __launch_bounds__(256, 2)
void gemm128(const float* __restrict__ A, const float* __restrict__ W,
             const float* __restrict__ bias, float* __restrict__ C,
             const float* __restrict__ al, const float* __restrict__ ar,
             float* __restrict__ elo, float* __restrict__ ero) {
    __shared__ float As[8][128];
    __shared__ float Ws[8][128];

    const int tid = threadIdx.x;
    const int tx = tid & 15;      // col group: cols tx*8 .. tx*8+7
    const int ty = tid >> 4;      // row group: rows ty*8 .. ty*8+7
    const int rb = blockIdx.x * 128;

    // load indices
    const int arow = tid >> 1;            // 0..127
    const int acol = (tid & 1) * 4;       // 0 or 4
    const int wrow = tid >> 5;            // 0..7
    const int wcol = (tid & 31) * 4;      // 0..124

    float acc[8][8];
#pragma unroll
    for (int i = 0; i < 8; i++)
#pragma unroll
        for (int j = 0; j < 8; j++) acc[i][j] = 0.f;

    for (int kc = 0; kc < 128; kc += 8) {
        float4 av = make_float4(0.f, 0.f, 0.f, 0.f);
        int gr = rb + arow;
        if (gr < N_NODES) av = *(const float4*)&A[(size_t)gr * NF + kc + acol];
        As[acol + 0][arow] = av.x;
        As[acol + 1][arow] = av.y;
        As[acol + 2][arow] = av.z;
        As[acol + 3][arow] = av.w;
        *(float4*)&Ws[wrow][wcol] = *(const float4*)&W[(kc + wrow) * NF + wcol];
        __syncthreads();
#pragma unroll
        for (int kk = 0; kk < 8; kk++) {
            float a[8], b[8];
            *(float4*)&a[0] = *(float4*)&As[kk][ty * 8];
            *(float4*)&a[4] = *(float4*)&As[kk][ty * 8 + 4];
            *(float4*)&b[0] = *(float4*)&Ws[kk][tx * 8];
            *(float4*)&b[4] = *(float4*)&Ws[kk][tx * 8 + 4];
#pragma unroll
            for (int i = 0; i < 8; i++)
#pragma unroll
                for (int j = 0; j < 8; j++)
                    acc[i][j] = fmaf(a[i], b[j], acc[i][j]);
        }
        __syncthreads();
    }

    const int cb = tx * 8;
    float bcol[8];
#pragma unroll
    for (int j = 0; j < 8; j++) bcol[j] = bias ? bias[cb + j] : 0.f;
    float alv[8], arv[8];
    if (elo) {
#pragma unroll
        for (int j = 0; j < 8; j++) { alv[j] = al[cb + j]; arv[j] = ar[cb + j]; }
    }
    const int hh = tx >> 2;   // 32 cols per head, 8 cols per thread

#pragma unroll
    for (int i = 0; i < 8; i++) {
        int row = rb + ty * 8 + i;
        if (row < N_NODES) {
            float4 o0 = make_float4(acc[i][0] + bcol[0], acc[i][1] + bcol[1],
                                    acc[i][2] + bcol[2], acc[i][3] + bcol[3]);
            float4 o1 = make_float4(acc[i][4] + bcol[4], acc[i][5] + bcol[5],
                                    acc[i][6] + bcol[6], acc[i][7] + bcol[7]);
            *(float4*)&C[(size_t)row * NF + cb]     = o0;
            *(float4*)&C[(size_t)row * NF + cb + 4] = o1;
        }
        if (elo) {
            float p = 0.f, q = 0.f;
#pragma unroll
            for (int j = 0; j < 8; j++) {
                p = fmaf(acc[i][j], alv[j], p);
                q = fmaf(acc[i][j], arv[j], q);
            }
            // reduce over 4 lanes covering one head (32 cols)
            p += __shfl_down_sync(0xffffffffu, p, 1, 4);
            p += __shfl_down_sync(0xffffffffu, p, 2, 4);
            q += __shfl_down_sync(0xffffffffu, q, 1, 4);
            q += __shfl_down_sync(0xffffffffu, q, 2, 4);
            if ((tx & 3) == 0 && row < N_NODES) {
                elo[row * NH + hh] = p;
                ero[row * NH + hh] = q;
            }
        }
    }
}

// ---------------- edge softmax passes ----------------
__device__ __forceinline__ void atomicMaxF(float* addr, float val) {
    if (val >= 0.f) atomicMax((int*)addr, __float_as_int(val));
    else            atomicMin((unsigned int*)addr, __float_as_uint(val));
}

__global__ void edge_max(const int* __restrict__ src, const int* __restrict__ dst,
                         const float* __restrict__ el, const float* __restrict__ er,
                         float* __restrict__ mx) {
    int idx = blockIdx.x * blockDim.x + threadIdx.x;
    if (idx >= N_EDGES * NH) return;
    int e = idx >> 2, h = idx & 3;
    int s = src[e], d = dst[e];
    float v = el[s * NH + h] + er[d * NH + h];
    v = v > 0.f ? v : NEG_SLOPE * v;
    atomicMaxF(&mx[d * NH + h], v);
}

__global__ void edge_sum(const int* __restrict__ src, const int* __restrict__ dst,
                         const float* __restrict__ el, const float* __restrict__ er,
                         const float* __restrict__ mx, float* __restrict__ ex,
                         float* __restrict__ sm) {
    int idx = blockIdx.x * blockDim.x + threadIdx.x;
    if (idx >= N_EDGES * NH) return;
    int e = idx >> 2, h = idx & 3;
    int s = src[e], d = dst[e];
    float v = el[s * NH + h] + er[d * NH + h];
    v = v > 0.f ? v : NEG_SLOPE * v;
    float t = expf(v - mx[d * NH + h]);
    ex[idx] = t;
    atomicAdd(&sm[d * NH + h], t);
}

// vectorized global reduction (sm_90+): one RED.128 instead of 4 RED.32
__device__ __forceinline__ void redAdd4(float* p, float a, float b, float c, float d) {
    asm volatile("red.global.add.v4.f32 [%0], {%1, %2, %3, %4};"
                 :: "l"(p), "f"(a), "f"(b), "f"(c), "f"(d) : "memory");
}

// one warp per edge: lane L handles fs columns L*4..L*4+3 (head = L>>3)
__global__ __launch_bounds__(256)
void edge_msg(const int* __restrict__ src, const int* __restrict__ dst,
              const float* __restrict__ fs, const float* __restrict__ ex,
              const float* __restrict__ sm, float* __restrict__ h2) {
    int gw = (blockIdx.x * blockDim.x + threadIdx.x) >> 5;
    int lane = threadIdx.x & 31;
    if (gw >= N_EDGES) return;
    int s = src[gw], d = dst[gw];
    int h = lane >> 3;
    float alpha = ex[gw * NH + h] / sm[d * NH + h];
    float4 f = *(const float4*)&fs[(size_t)s * NF + lane * 4];
    redAdd4(&h2[(size_t)d * NF + lane * 4],
            alpha * f.x, alpha * f.y, alpha * f.z, alpha * f.w);
}

// ---------------- layer finalize: t = h1 + relu(h2 + bias), + BN stats -----
#define RPB 128
__global__ void finalize_stats(const float* __restrict__ h1, const float* __restrict__ h2,
                               const float* __restrict__ cb0, const float* __restrict__ cb1,
                               float* __restrict__ t) {
    int col = threadIdx.x;
    float bias = cb0[col] + cb1[col];
    int r0 = blockIdx.x * RPB;
    double s = 0.0, s2 = 0.0;
    for (int r = 0; r < RPB; r++) {
        int row = r0 + r;
        if (row >= N_NODES) break;
        float v = h2[(size_t)row * NF + col] + bias;
        v = v > 0.f ? v : 0.f;
        v += h1[(size_t)row * NF + col];
        t[(size_t)row * NF + col] = v;
        s += v;
        s2 += (double)v * (double)v;
    }
    atomicAdd(&g_sum[col], s);
    atomicAdd(&g_sq[col], s2);
}

__global__ void stats128(const float* __restrict__ x) {
    int col = threadIdx.x;
    int r0 = blockIdx.x * RPB;
    double s = 0.0, s2 = 0.0;
    for (int r = 0; r < RPB; r++) {
        int row = r0 + r;
        if (row >= N_NODES) break;
        float v = x[(size_t)row * NF + col];
        s += v;
        s2 += (double)v * (double)v;
    }
    atomicAdd(&g_sum[col], s);
    atomicAdd(&g_sq[col], s2);
}

__global__ void normalize128(const float* __restrict__ x, const float* __restrict__ g,
                             const float* __restrict__ b, float* __restrict__ y,
                             int do_relu) {
    int col = threadIdx.x;
    double mu = g_sum[col] / (double)N_NODES;
    double var = g_sq[col] / (double)N_NODES - mu * mu;
    float sc = g[col] * rsqrtf((float)var + BN_EPS);
    float sh = b[col] - (float)mu * sc;
    int r0 = blockIdx.x * RPB;
    for (int r = 0; r < RPB; r++) {
        int row = r0 + r;
        if (row >= N_NODES) break;
        float v = x[(size_t)row * NF + col] * sc + sh;
        if (do_relu) v = v > 0.f ? v : 0.f;
        y[(size_t)row * NF + col] = v;
    }
}

// ---------------- final 128 -> 16 GEMM ----------------
__global__ __launch_bounds__(128)
void gemm_out(const float* __restrict__ x, const float* __restrict__ W2,
              const float* __restrict__ b2, float* __restrict__ out) {
    __shared__ float xs[8][NF];
    int tid = threadIdx.x;
    int r0 = blockIdx.x * 8;
#pragma unroll
    for (int i = 0; i < 8; i++) {
        int row = r0 + i;
        xs[i][tid] = (row < N_NODES) ? x[(size_t)row * NF + tid] : 0.f;
    }
    __syncthreads();
    int row = tid >> 4;
    int c = tid & 15;
    float acc = b2[c];
#pragma unroll 8
    for (int k = 0; k < NF; k++) acc = fmaf(xs[row][k], W2[k * 16 + c], acc);
    if (r0 + row < N_NODES) out[(size_t)(r0 + row) * 16 + c] = acc;
}

// ---------------- host ----------------
extern "C" void kernel_launch(void* const* d_in, const int* in_sizes, int n_in,
                              void* d_out, int out_size) {
    const float* feat     = (const float*)d_in[0];
    const float* fc_W     = (const float*)d_in[1];   // [2][2][128][128]
    const float* attn_l   = (const float*)d_in[2];   // [2][2][4][32] -> [..][128]
    const float* attn_r   = (const float*)d_in[3];
    const float* conv_b   = (const float*)d_in[4];   // [2][2][128]
    const float* skip_W   = (const float*)d_in[5];   // [2][128][128]
    const float* skip_b   = (const float*)d_in[6];   // [2][128]
    const float* norm_g   = (const float*)d_in[7];
    const float* norm_b   = (const float*)d_in[8];
    const float* clf_W1   = (const float*)d_in[9];
    const float* clf_b1   = (const float*)d_in[10];
    const float* clf_g    = (const float*)d_in[11];
    const float* clf_b    = (const float*)d_in[12];
    const float* clf_W2   = (const float*)d_in[13];
    const float* clf_b2   = (const float*)d_in[14];
    const int*   src      = (const int*)d_in[15];    // [2][500000]
    const int*   dst      = (const int*)d_in[16];
    float* out = (float*)d_out;

    float *h, *h1, *fs, *h2, *el, *er, *mx, *sm, *ex;
    cudaGetSymbolAddress((void**)&h,  g_h);
    cudaGetSymbolAddress((void**)&h1, g_h1);
    cudaGetSymbolAddress((void**)&fs, g_fs);
    cudaGetSymbolAddress((void**)&h2, g_h2);
    cudaGetSymbolAddress((void**)&el, g_el);
    cudaGetSymbolAddress((void**)&er, g_er);
    cudaGetSymbolAddress((void**)&mx, g_mx);
    cudaGetSymbolAddress((void**)&sm, g_sm);
    cudaGetSymbolAddress((void**)&ex, g_ex);

    const int gemm_grid = (N_NODES + 127) / 128;           // 391
    const int eh_grid   = (N_EDGES * NH + 255) / 256;      // 7813
    const int msg_grid  = (N_EDGES * 32 + 255) / 256;      // 62500
    const int fill_big  = (N_NODES * NF / 4 + 255) / 256;
    const int fill_sm   = (N_NODES * NH / 4 + 255) / 256;
    const int bn_grid   = (N_NODES + RPB - 1) / RPB;       // 391

    const float* hin = feat;
    for (int l = 0; l < 2; l++) {
        // skip linear: h1 = hin @ skip_W[l] + skip_b[l]
        gemm128<<<gemm_grid, 256>>>(hin, skip_W + l * NF * NF, skip_b + l * NF,
                                    h1, nullptr, nullptr, nullptr, nullptr);
        fill_f4<<<fill_big, 256>>>((float4*)h2, 0.f, N_NODES * NF / 4);

        for (int r = 0; r < 2; r++) {
            int lr = l * 2 + r;
            // fs = hin @ fc_W[l,r]; el/er fused in epilogue
            gemm128<<<gemm_grid, 256>>>(hin, fc_W + (size_t)lr * NF * NF, nullptr,
                                        fs, attn_l + lr * NF, attn_r + lr * NF, el, er);
            fill_f4<<<fill_sm, 256>>>((float4*)mx, -INFINITY, N_NODES * NH / 4);
            fill_f4<<<fill_sm, 256>>>((float4*)sm, 0.f, N_NODES * NH / 4);
            const int* sr = src + (size_t)r * N_EDGES;
            const int* dr = dst + (size_t)r * N_EDGES;
            edge_max<<<eh_grid, 256>>>(sr, dr, el, er, mx);
            edge_sum<<<eh_grid, 256>>>(sr, dr, el, er, mx, ex, sm);
            edge_msg<<<msg_grid, 256>>>(sr, dr, fs, ex, sm, h2);
        }

        zero_stats<<<1, 128>>>();
        // t = h1 + relu(h2 + sum_r conv_bias) (into fs scratch) + BN stats
        finalize_stats<<<bn_grid, 128>>>(h1, h2, conv_b + (l * 2 + 0) * NF,
                                         conv_b + (l * 2 + 1) * NF, fs);
        normalize128<<<bn_grid, 128>>>(fs, norm_g + l * NF, norm_b + l * NF, h, 0);
        hin = h;
    }

    // classifier
    gemm128<<<gemm_grid, 256>>>(h, clf_W1, clf_b1, h1, nullptr, nullptr, nullptr, nullptr);
    zero_stats<<<1, 128>>>();
    stats128<<<bn_grid, 128>>>(h1);
    normalize128<<<bn_grid, 128>>>(h1, clf_g, clf_b, fs, 1);
    gemm_out<<<(N_NODES + 7) / 8, 128>>>(fs, clf_W2, clf_b2, out);
}

// round 3
// speedup vs baseline: 1.5025x; 1.1382x over previous
#include <cuda_runtime.h>
#include <math.h>

#define N_NODES 50000
#define N_EDGES 500000
#define NF      128
#define NH      4
#define NEG_SLOPE 0.2f
#define BN_EPS 1e-5f
#define SCAN_B  1024
#define N_SCANB ((N_NODES + SCAN_B - 1) / SCAN_B)   // 49

// ---------------- scratch (device globals; no allocation allowed) ----------
__device__ float g_h  [N_NODES * NF];
__device__ float g_h1 [N_NODES * NF];
__device__ float g_fs [N_NODES * NF];
__device__ float g_h2a[N_NODES * NF];
__device__ float g_h2b[N_NODES * NF];
__device__ float g_el [N_NODES * NH];
__device__ float g_er [N_NODES * NH];
__device__ double g_sum[NF];
__device__ double g_sq [NF];
// CSR (2 relations)
__device__ int g_deg   [2][N_NODES];
__device__ int g_rowptr[2][N_NODES + 1];
__device__ int g_cursor[2][N_NODES];
__device__ int g_colsrc[2][N_EDGES];
__device__ int g_bsum  [2][N_SCANB];

// ---------------- small utility kernels ----------------
__global__ void zero_stats() {
    g_sum[threadIdx.x] = 0.0;
    g_sq[threadIdx.x]  = 0.0;
}

__global__ void zero_deg(int r) {
    int i = blockIdx.x * blockDim.x + threadIdx.x;
    if (i < N_NODES) g_deg[r][i] = 0;
}

// ---------------- CSR build ----------------
__global__ void hist_deg(const int* __restrict__ dst, int r) {
    int e = blockIdx.x * blockDim.x + threadIdx.x;
    if (e < N_EDGES) atomicAdd(&g_deg[r][dst[e]], 1);
}

__global__ __launch_bounds__(SCAN_B)
void scan_blocks(int r) {
    __shared__ int tmp[SCAN_B];
    int i = blockIdx.x * SCAN_B + threadIdx.x;
    int v = (i < N_NODES) ? g_deg[r][i] : 0;
    tmp[threadIdx.x] = v;
    __syncthreads();
    for (int off = 1; off < SCAN_B; off <<= 1) {
        int t = (threadIdx.x >= off) ? tmp[threadIdx.x - off] : 0;
        __syncthreads();
        tmp[threadIdx.x] += t;
        __syncthreads();
    }
    if (i < N_NODES) g_rowptr[r][i] = tmp[threadIdx.x] - v;   // exclusive
    if (threadIdx.x == SCAN_B - 1) g_bsum[r][blockIdx.x] = tmp[SCAN_B - 1];
}

__global__ void scan_bsum(int r) {
    __shared__ int s[64];
    int v = (threadIdx.x < N_SCANB) ? g_bsum[r][threadIdx.x] : 0;
    s[threadIdx.x] = v;
    __syncthreads();
    for (int off = 1; off < 64; off <<= 1) {
        int t = (threadIdx.x >= off) ? s[threadIdx.x - off] : 0;
        __syncthreads();
        s[threadIdx.x] += t;
        __syncthreads();
    }
    if (threadIdx.x < N_SCANB) g_bsum[r][threadIdx.x] = s[threadIdx.x] - v;  // exclusive
}

__global__ void scan_finish(int r) {
    int i = blockIdx.x * blockDim.x + threadIdx.x;
    if (i < N_NODES) {
        int v = g_rowptr[r][i] + g_bsum[r][i / SCAN_B];
        g_rowptr[r][i] = v;
        g_cursor[r][i] = v;
    }
    if (i == 0) g_rowptr[r][N_NODES] = N_EDGES;
}

__global__ void scatter_csr(const int* __restrict__ src, const int* __restrict__ dst, int r) {
    int e = blockIdx.x * blockDim.x + threadIdx.x;
    if (e >= N_EDGES) return;
    int p = atomicAdd(&g_cursor[r][dst[e]], 1);
    g_colsrc[r][p] = src[e];
}

// ---------------- 50000x128 @ 128x128 SGEMM (+ optional attn epilogue) -----
// BM=128, BN=128, BK=8, 256 threads, 8x8 microtile.
__global__ __launch_bounds__(256, 2)
void gemm128(const float* __restrict__ A, const float* __restrict__ W,
             const float* __restrict__ bias, float* __restrict__ C,
             const float* __restrict__ al, const float* __restrict__ ar,
             float* __restrict__ elo, float* __restrict__ ero) {
    __shared__ float As[8][128];
    __shared__ float Ws[8][128];

    const int tid = threadIdx.x;
    const int tx = tid & 15;
    const int ty = tid >> 4;
    const int rb = blockIdx.x * 128;

    const int arow = tid >> 1;
    const int acol = (tid & 1) * 4;
    const int wrow = tid >> 5;
    const int wcol = (tid & 31) * 4;

    float acc[8][8];
#pragma unroll
    for (int i = 0; i < 8; i++)
#pragma unroll
        for (int j = 0; j < 8; j++) acc[i][j] = 0.f;

    for (int kc = 0; kc < 128; kc += 8) {
        float4 av = make_float4(0.f, 0.f, 0.f, 0.f);
        int gr = rb + arow;
        if (gr < N_NODES) av = *(const float4*)&A[(size_t)gr * NF + kc + acol];
        As[acol + 0][arow] = av.x;
        As[acol + 1][arow] = av.y;
        As[acol + 2][arow] = av.z;
        As[acol + 3][arow] = av.w;
        *(float4*)&Ws[wrow][wcol] = *(const float4*)&W[(kc + wrow) * NF + wcol];
        __syncthreads();
#pragma unroll
        for (int kk = 0; kk < 8; kk++) {
            float a[8], b[8];
            *(float4*)&a[0] = *(float4*)&As[kk][ty * 8];
            *(float4*)&a[4] = *(float4*)&As[kk][ty * 8 + 4];
            *(float4*)&b[0] = *(float4*)&Ws[kk][tx * 8];
            *(float4*)&b[4] = *(float4*)&Ws[kk][tx * 8 + 4];
#pragma unroll
            for (int i = 0; i < 8; i++)
#pragma unroll
                for (int j = 0; j < 8; j++)
                    acc[i][j] = fmaf(a[i], b[j], acc[i][j]);
        }
        __syncthreads();
    }

    const int cb = tx * 8;
    float bcol[8];
#pragma unroll
    for (int j = 0; j < 8; j++) bcol[j] = bias ? bias[cb + j] : 0.f;
    float alv[8], arv[8];
    if (elo) {
#pragma unroll
        for (int j = 0; j < 8; j++) { alv[j] = al[cb + j]; arv[j] = ar[cb + j]; }
    }
    const int hh = tx >> 2;

#pragma unroll
    for (int i = 0; i < 8; i++) {
        int row = rb + ty * 8 + i;
        if (row < N_NODES) {
            float4 o0 = make_float4(acc[i][0] + bcol[0], acc[i][1] + bcol[1],
                                    acc[i][2] + bcol[2], acc[i][3] + bcol[3]);
            float4 o1 = make_float4(acc[i][4] + bcol[4], acc[i][5] + bcol[5],
                                    acc[i][6] + bcol[6], acc[i][7] + bcol[7]);
            *(float4*)&C[(size_t)row * NF + cb]     = o0;
            *(float4*)&C[(size_t)row * NF + cb + 4] = o1;
        }
        if (elo) {
            float p = 0.f, q = 0.f;
#pragma unroll
            for (int j = 0; j < 8; j++) {
                p = fmaf(acc[i][j], alv[j], p);
                q = fmaf(acc[i][j], arv[j], q);
            }
            p += __shfl_down_sync(0xffffffffu, p, 1, 4);
            p += __shfl_down_sync(0xffffffffu, p, 2, 4);
            q += __shfl_down_sync(0xffffffffu, q, 1, 4);
            q += __shfl_down_sync(0xffffffffu, q, 2, 4);
            if ((tx & 3) == 0 && row < N_NODES) {
                elo[row * NH + hh] = p;
                ero[row * NH + hh] = q;
            }
        }
    }
}

// ---------------- fused GAT aggregation: warp per dst node ----------------
// phase1: per-head sum of exp(leaky(el[src]+er[d])); phase2: acc alpha*fs[src].
__global__ __launch_bounds__(256)
void gat_agg(int r, const float* __restrict__ el, const float* __restrict__ er,
             const float* __restrict__ fs, float* __restrict__ h2) {
    int d = (blockIdx.x * blockDim.x + threadIdx.x) >> 5;
    int lane = threadIdx.x & 31;
    if (d >= N_NODES) return;
    const int beg = g_rowptr[r][d];
    const int end = g_rowptr[r][d + 1];
    const float4 erd = *(const float4*)&er[d * NH];

    // phase 1: per-head sum of exp
    float s0 = 0.f, s1 = 0.f, s2 = 0.f, s3 = 0.f;
    for (int e = beg + lane; e < end; e += 32) {
        int s = g_colsrc[r][e];
        float4 elv = *(const float4*)&el[s * NH];
        float e0 = elv.x + erd.x; e0 = e0 > 0.f ? e0 : NEG_SLOPE * e0;
        float e1 = elv.y + erd.y; e1 = e1 > 0.f ? e1 : NEG_SLOPE * e1;
        float e2 = elv.z + erd.z; e2 = e2 > 0.f ? e2 : NEG_SLOPE * e2;
        float e3 = elv.w + erd.w; e3 = e3 > 0.f ? e3 : NEG_SLOPE * e3;
        s0 += expf(e0); s1 += expf(e1); s2 += expf(e2); s3 += expf(e3);
    }
#pragma unroll
    for (int off = 16; off >= 1; off >>= 1) {
        s0 += __shfl_xor_sync(0xffffffffu, s0, off);
        s1 += __shfl_xor_sync(0xffffffffu, s1, off);
        s2 += __shfl_xor_sync(0xffffffffu, s2, off);
        s3 += __shfl_xor_sync(0xffffffffu, s3, off);
    }

    // phase 2: weighted accumulate; lane covers fs cols lane*4..lane*4+3
    const int h = lane >> 3;
    const float er_h = (h == 0) ? erd.x : (h == 1) ? erd.y : (h == 2) ? erd.z : erd.w;
    const float s_h  = (h == 0) ? s0    : (h == 1) ? s1    : (h == 2) ? s2    : s3;
    const float inv_s = (end > beg) ? (1.f / s_h) : 0.f;

    float4 acc = make_float4(0.f, 0.f, 0.f, 0.f);
    for (int e = beg; e < end; e++) {
        int s = g_colsrc[r][e];                 // broadcast
        float4 elv = *(const float4*)&el[s * NH];
        float el_h = (h == 0) ? elv.x : (h == 1) ? elv.y : (h == 2) ? elv.z : elv.w;
        float ev = el_h + er_h;
        ev = ev > 0.f ? ev : NEG_SLOPE * ev;
        float alpha = expf(ev) * inv_s;
        float4 f = *(const float4*)&fs[(size_t)s * NF + lane * 4];
        acc.x = fmaf(alpha, f.x, acc.x);
        acc.y = fmaf(alpha, f.y, acc.y);
        acc.z = fmaf(alpha, f.z, acc.z);
        acc.w = fmaf(alpha, f.w, acc.w);
    }
    *(float4*)&h2[(size_t)d * NF + lane * 4] = acc;
}

// ---------------- layer finalize: t = h1 + relu(h2a+h2b+bias), + BN stats --
#define RPB 128
__global__ void finalize_stats(const float* __restrict__ h1,
                               const float* __restrict__ h2a,
                               const float* __restrict__ h2b,
                               const float* __restrict__ cb0,
                               const float* __restrict__ cb1,
                               float* __restrict__ t) {
    int col = threadIdx.x;
    float bias = cb0[col] + cb1[col];
    int r0 = blockIdx.x * RPB;
    double s = 0.0, s2 = 0.0;
    for (int r = 0; r < RPB; r++) {
        int row = r0 + r;
        if (row >= N_NODES) break;
        float v = h2a[(size_t)row * NF + col] + h2b[(size_t)row * NF + col] + bias;
        v = v > 0.f ? v : 0.f;
        v += h1[(size_t)row * NF + col];
        t[(size_t)row * NF + col] = v;
        s += v;
        s2 += (double)v * (double)v;
    }
    atomicAdd(&g_sum[col], s);
    atomicAdd(&g_sq[col], s2);
}

__global__ void stats128(const float* __restrict__ x) {
    int col = threadIdx.x;
    int r0 = blockIdx.x * RPB;
    double s = 0.0, s2 = 0.0;
    for (int r = 0; r < RPB; r++) {
        int row = r0 + r;
        if (row >= N_NODES) break;
        float v = x[(size_t)row * NF + col];
        s += v;
        s2 += (double)v * (double)v;
    }
    atomicAdd(&g_sum[col], s);
    atomicAdd(&g_sq[col], s2);
}

__global__ void normalize128(const float* __restrict__ x, const float* __restrict__ g,
                             const float* __restrict__ b, float* __restrict__ y,
                             int do_relu) {
    int col = threadIdx.x;
    double mu = g_sum[col] / (double)N_NODES;
    double var = g_sq[col] / (double)N_NODES - mu * mu;
    float sc = g[col] * rsqrtf((float)var + BN_EPS);
    float sh = b[col] - (float)mu * sc;
    int r0 = blockIdx.x * RPB;
    for (int r = 0; r < RPB; r++) {
        int row = r0 + r;
        if (row >= N_NODES) break;
        float v = x[(size_t)row * NF + col] * sc + sh;
        if (do_relu) v = v > 0.f ? v : 0.f;
        y[(size_t)row * NF + col] = v;
    }
}

// ---------------- final 128 -> 16 GEMM ----------------
__global__ __launch_bounds__(128)
void gemm_out(const float* __restrict__ x, const float* __restrict__ W2,
              const float* __restrict__ b2, float* __restrict__ out) {
    __shared__ float xs[8][NF];
    int tid = threadIdx.x;
    int r0 = blockIdx.x * 8;
#pragma unroll
    for (int i = 0; i < 8; i++) {
        int row = r0 + i;
        xs[i][tid] = (row < N_NODES) ? x[(size_t)row * NF + tid] : 0.f;
    }
    __syncthreads();
    int row = tid >> 4;
    int c = tid & 15;
    float acc = b2[c];
#pragma unroll 8
    for (int k = 0; k < NF; k++) acc = fmaf(xs[row][k], W2[k * 16 + c], acc);
    if (r0 + row < N_NODES) out[(size_t)(r0 + row) * 16 + c] = acc;
}

// ---------------- host ----------------
extern "C" void kernel_launch(void* const* d_in, const int* in_sizes, int n_in,
                              void* d_out, int out_size) {
    const float* feat     = (const float*)d_in[0];
    const float* fc_W     = (const float*)d_in[1];
    const float* attn_l   = (const float*)d_in[2];
    const float* attn_r   = (const float*)d_in[3];
    const float* conv_b   = (const float*)d_in[4];
    const float* skip_W   = (const float*)d_in[5];
    const float* skip_b   = (const float*)d_in[6];
    const float* norm_g   = (const float*)d_in[7];
    const float* norm_b   = (const float*)d_in[8];
    const float* clf_W1   = (const float*)d_in[9];
    const float* clf_b1   = (const float*)d_in[10];
    const float* clf_g    = (const float*)d_in[11];
    const float* clf_b    = (const float*)d_in[12];
    const float* clf_W2   = (const float*)d_in[13];
    const float* clf_b2   = (const float*)d_in[14];
    const int*   src      = (const int*)d_in[15];
    const int*   dst      = (const int*)d_in[16];
    float* out = (float*)d_out;

    float *h, *h1, *fs, *h2a, *h2b, *el, *er;
    cudaGetSymbolAddress((void**)&h,   g_h);
    cudaGetSymbolAddress((void**)&h1,  g_h1);
    cudaGetSymbolAddress((void**)&fs,  g_fs);
    cudaGetSymbolAddress((void**)&h2a, g_h2a);
    cudaGetSymbolAddress((void**)&h2b, g_h2b);
    cudaGetSymbolAddress((void**)&el,  g_el);
    cudaGetSymbolAddress((void**)&er,  g_er);

    const int gemm_grid = (N_NODES + 127) / 128;
    const int node_grid = (N_NODES + 255) / 256;
    const int edge_grid = (N_EDGES + 255) / 256;
    const int agg_grid  = (N_NODES * 32 + 255) / 256;
    const int bn_grid   = (N_NODES + RPB - 1) / RPB;

    // ---- CSR build (once, reused by both layers) ----
    for (int r = 0; r < 2; r++) {
        const int* dr = dst + (size_t)r * N_EDGES;
        const int* sr = src + (size_t)r * N_EDGES;
        zero_deg<<<node_grid, 256>>>(r);
        hist_deg<<<edge_grid, 256>>>(dr, r);
        scan_blocks<<<N_SCANB, SCAN_B>>>(r);
        scan_bsum<<<1, 64>>>(r);
        scan_finish<<<node_grid, 256>>>(r);
        scatter_csr<<<edge_grid, 256>>>(sr, dr, r);
    }

    const float* hin = feat;
    for (int l = 0; l < 2; l++) {
        gemm128<<<gemm_grid, 256>>>(hin, skip_W + l * NF * NF, skip_b + l * NF,
                                    h1, nullptr, nullptr, nullptr, nullptr);
        for (int r = 0; r < 2; r++) {
            int lr = l * 2 + r;
            gemm128<<<gemm_grid, 256>>>(hin, fc_W + (size_t)lr * NF * NF, nullptr,
                                        fs, attn_l + lr * NF, attn_r + lr * NF, el, er);
            gat_agg<<<agg_grid, 256>>>(r, el, er, fs, r == 0 ? h2a : h2b);
        }
        zero_stats<<<1, 128>>>();
        finalize_stats<<<bn_grid, 128>>>(h1, h2a, h2b,
                                         conv_b + (l * 2 + 0) * NF,
                                         conv_b + (l * 2 + 1) * NF, fs);
        normalize128<<<bn_grid, 128>>>(fs, norm_g + l * NF, norm_b + l * NF, h, 0);
        hin = h;
    }

    // classifier
    gemm128<<<gemm_grid, 256>>>(h, clf_W1, clf_b1, h1, nullptr, nullptr, nullptr, nullptr);
    zero_stats<<<1, 128>>>();
    stats128<<<bn_grid, 128>>>(h1);
    normalize128<<<bn_grid, 128>>>(h1, clf_g, clf_b, fs, 1);
    gemm_out<<<(N_NODES + 7) / 8, 128>>>(fs, clf_W2, clf_b2, out);
}